// round 12
// baseline (speedup 1.0000x reference)
#include <cuda_runtime.h>
#include <cstdint>

// ESN: s_t = tanh(U_t + W_res @ s_{t-1}),  U = X @ W_in^T
// T=16384 steps, R=1024 reservoir, I=128 input. W_res ~5% dense.
//
// R11 vs R7 (8.66ms best). R10 proved 16 CTAs is strictly worse (fabric
// cost ~34cyc/peer); 8-CTA structure is final. Two safe tweaks on R7:
//  - KREG 40 -> 36 (72-element register gather; ~10% less crossbar pad),
//    SREM 24 -> 28 keeps the 64-pair clamp for the smem remainder path.
//  - out[] STG + u_next LDG moved into the mbarrier-wait shadow
//    (after arrives, before try_wait).
// Everything else byte-identical to R7.

#define T_STEPS 16384
#define R_DIM   1024
#define I_DIM   128
#define NCTA    8
#define RPC     128     // rows per CTA == threads per CTA
#define ELLCAP  192     // max slots per row (global build clamp)
#define KREG    36      // pairs held in registers per thread
#define SREM    28      // extra pairs staged in smem (KREG+SREM = 64 = clamp)

__device__ float    d_U[(size_t)T_STEPS * R_DIM];        // 64 MiB
__device__ float2   d_ellv2[(ELLCAP / 2) * R_DIM];       // pair-packed vals
__device__ unsigned d_ellc2[(ELLCAP / 2) * R_DIM];       // pair-packed BYTE offsets (2xu16)
__device__ int      d_kgrp[R_DIM / 32];                  // slots per 32-row group (even)

__device__ __forceinline__ uint32_t smaddr(const void* p) {
    uint32_t a;
    asm("{ .reg .u64 t; cvta.to.shared.u64 t, %1; cvt.u32.u64 %0, t; }"
        : "=r"(a) : "l"(p));
    return a;
}

// ---------------------------------------------------------------------------
// Fused prep kernel: blocks [0,32) build the bank-conflict-free ELL schedule
// (one warp per 32-row group); blocks [32, 32+4096) compute U = X @ W_in^T.
#define B2_BCOL 0
#define B2_BVAL (32 * 32 * 16 * 2)
#define B2_BCNT (B2_BVAL + 32 * 32 * 16 * 4)
#define B2_MASK (B2_BCNT + 32 * 32 * 4)
#define B2_SMEM (B2_MASK + 32 * 4)
#define GEMM_TILES_T (T_STEPS / 64)
#define GEMM_TILES_R (R_DIM / 64)
#define PREP_BLOCKS (32 + GEMM_TILES_T * GEMM_TILES_R)

__global__ __launch_bounds__(256) void k_prep(const float* __restrict__ W,
                                              const float* __restrict__ X,
                                              const float* __restrict__ Win) {
    if (blockIdx.x < 32) {
        if (threadIdx.x >= 32) return;
        extern __shared__ unsigned char sm[];
        unsigned short* bcol    = (unsigned short*)(sm + B2_BCOL);  // [r][b][16]
        float*          bval    = (float*)(sm + B2_BVAL);           // [r][b][16]
        int*            bcnt    = (int*)(sm + B2_BCNT);             // [r][b]
        unsigned*       rowmask = (unsigned*)(sm + B2_MASK);        // [r]

        int g = blockIdx.x;
        int r = threadIdx.x;  // 0..31

        for (int b = 0; b < 32; b++) bcnt[r * 32 + b] = 0;
        const float4* Wr4 = (const float4*)(W + (size_t)(g * 32 + r) * R_DIM);
        for (int c4 = 0; c4 < R_DIM / 4; c4++) {
            float4 w4 = Wr4[c4];
            float wv[4] = {w4.x, w4.y, w4.z, w4.w};
#pragma unroll
            for (int j = 0; j < 4; j++) {
                float w = wv[j];
                if (w != 0.0f) {
                    int c = c4 * 4 + j;
                    int b = c & 31;
                    int i = bcnt[r * 32 + b]++;
                    if (i < 16) {
                        bcol[(r * 32 + b) * 16 + i] = (unsigned short)c;
                        bval[(r * 32 + b) * 16 + i] = w;
                    }
                }
            }
        }
        unsigned m = 0;
        for (int b = 0; b < 32; b++)
            if (bcnt[r * 32 + b] > 0) m |= 1u << b;
        rowmask[r] = m;
        __syncwarp();

        if (r == 0) {
            int rows_left = 0;
            for (int i = 0; i < 32; i++)
                if (rowmask[i]) rows_left++;
            int s = 0;
            while (rows_left > 0 && s < ELLCAP) {
                unsigned used = 0, pickedmask = 0;
                for (int i = 0; i < 32; i++) {
                    int rr = (s + i) & 31;
                    unsigned avail = rowmask[rr] & ~used;
                    if (avail) {
                        int b = __ffs(avail) - 1;
                        int c = --bcnt[rr * 32 + b];
                        unsigned short col = bcol[(rr * 32 + b) * 16 + c];
                        float v = bval[(rr * 32 + b) * 16 + c];
                        if (c == 0) {
                            rowmask[rr] &= ~(1u << b);
                            if (!rowmask[rr]) rows_left--;
                        }
                        used |= 1u << b;
                        pickedmask |= 1u << rr;
                        size_t idx = (size_t)(s >> 1) * R_DIM + g * 32 + rr;
                        ((float*)d_ellv2)[idx * 2 + (s & 1)] = v;
                        ((unsigned short*)d_ellc2)[idx * 2 + (s & 1)] =
                            (unsigned short)(col * 4);  // BYTE offset
                    }
                }
                unsigned freeb = ~used;
                for (int rr = 0; rr < 32; rr++) {
                    if (!((pickedmask >> rr) & 1)) {
                        int b = __ffs(freeb) - 1;
                        freeb &= freeb - 1;
                        size_t idx = (size_t)(s >> 1) * R_DIM + g * 32 + rr;
                        ((float*)d_ellv2)[idx * 2 + (s & 1)] = 0.0f;
                        ((unsigned short*)d_ellc2)[idx * 2 + (s & 1)] =
                            (unsigned short)(b * 4);
                    }
                }
                s++;
            }
            if (s & 1) {  // pad to even slot count; pads bank-distinct
                for (int rr = 0; rr < 32; rr++) {
                    size_t idx = (size_t)(s >> 1) * R_DIM + g * 32 + rr;
                    ((float*)d_ellv2)[idx * 2 + 1] = 0.0f;
                    ((unsigned short*)d_ellc2)[idx * 2 + 1] = (unsigned short)(rr * 4);
                }
                s++;
            }
            d_kgrp[g] = s;
        }
        return;
    }

    // ---------------- gemm path: U = X @ W_in^T, 64x64 tiles ---------------
    __shared__ float xs[64][68];
    __shared__ float ws[64][68];
    int gb = blockIdx.x - 32;
    int bt = (gb % GEMM_TILES_T) * 64;
    int br = (gb / GEMM_TILES_T) * 64;
    int ty = threadIdx.x >> 4;
    int tx = threadIdx.x & 15;

    float acc[4][4];
#pragma unroll
    for (int i = 0; i < 4; i++)
#pragma unroll
        for (int j = 0; j < 4; j++) acc[i][j] = 0.0f;

    for (int kc = 0; kc < I_DIM; kc += 64) {
        for (int i = threadIdx.x; i < 64 * 16; i += 256) {
            int rr = i >> 4, cc = i & 15;
            *(float4*)&xs[rr][cc * 4] = *(const float4*)&X[(size_t)(bt + rr) * I_DIM + kc + cc * 4];
            *(float4*)&ws[rr][cc * 4] = *(const float4*)&Win[(size_t)(br + rr) * I_DIM + kc + cc * 4];
        }
        __syncthreads();
#pragma unroll
        for (int k = 0; k < 64; k++) {
            float a[4], b[4];
#pragma unroll
            for (int i = 0; i < 4; i++) a[i] = xs[ty + 16 * i][k];
#pragma unroll
            for (int j = 0; j < 4; j++) b[j] = ws[tx + 16 * j][k];
#pragma unroll
            for (int i = 0; i < 4; i++)
#pragma unroll
                for (int j = 0; j < 4; j++) acc[i][j] += a[i] * b[j];
        }
        __syncthreads();
    }
#pragma unroll
    for (int i = 0; i < 4; i++)
#pragma unroll
        for (int j = 0; j < 4; j++)
            d_U[(size_t)(bt + ty + 16 * i) * R_DIM + br + tx + 16 * j] = acc[i][j];
}

// ---------------------------------------------------------------------------
// Recurrence: 8-CTA cluster, 128 threads (4 warps), one FULL row per thread.
__global__ __launch_bounds__(RPC, 1)
void k_esn(const float* __restrict__ state0, float* __restrict__ out) {
    __shared__ float    sbuf[2 * R_DIM];          // double-buffered full state
    __shared__ float2   srv[SREM][RPC];           // remainder pairs (vals)
    __shared__ unsigned src_[SREM][RPC];          // remainder pairs (byte-off pairs)
    __shared__ unsigned long long mbar[2];
    __shared__ int kg_s[4];

    int tid = threadIdx.x;          // 0..127
    int cta = blockIdx.x;           // == cluster rank
    int grow = cta * RPC + tid;     // global row owned by this thread

    uint32_t sb_a = smaddr(sbuf);
    uint32_t mb_a = smaddr(mbar);

    if (tid < 4) {
        int v = d_kgrp[cta * 4 + tid];
        kg_s[tid] = (v > 2 * (KREG + SREM)) ? 2 * (KREG + SREM) : v;
    }
    if (tid == 0) {
        // 8 arrivals per phase barrier: one per source CTA
        asm volatile("mbarrier.init.shared.b64 [%0], %1;" :: "r"(mb_a), "r"(NCTA));
        asm volatile("mbarrier.init.shared.b64 [%0], %1;" :: "r"(mb_a + 8), "r"(NCTA));
    }
    for (int i = tid; i < R_DIM; i += RPC) sbuf[i] = state0[i];
    __syncthreads();

    // stage remainder pairs [KREG, Kp) into smem
    for (int idx = tid; idx < SREM * RPC; idx += RPC) {
        int p = KREG + idx / RPC, lr = idx % RPC;
        int kp2 = kg_s[lr >> 5] >> 1;
        if (p < kp2) {
            srv[p - KREG][lr] = d_ellv2[(size_t)p * R_DIM + cta * RPC + lr];
            src_[p - KREG][lr] = d_ellc2[(size_t)p * R_DIM + cta * RPC + lr];
        }
    }
    __syncthreads();

    // all CTAs' mbarrier.init + initial state complete before use
    asm volatile("barrier.cluster.arrive.aligned;" ::: "memory");
    asm volatile("barrier.cluster.wait.aligned;" ::: "memory");

    int Kp = kg_s[tid >> 5] >> 1;   // pair count for my row's group

    // ---- preload: values + ABSOLUTE smem addresses (buffer 0) ------------
    float    va[2 * KREG];
    uint32_t ad[2 * KREG];
    uint32_t pada = sb_a + (uint32_t)((tid & 31) * 4);  // lane-distinct pad bank
#pragma unroll
    for (int p = 0; p < KREG; p++) {
        if (p < Kp) {
            float2 v = d_ellv2[(size_t)p * R_DIM + grow];
            unsigned c = d_ellc2[(size_t)p * R_DIM + grow];
            va[2 * p] = v.x;     ad[2 * p] = sb_a + (c & 0xFFFFu);
            va[2 * p + 1] = v.y; ad[2 * p + 1] = sb_a + (c >> 16);
        } else {
            va[2 * p] = 0.0f;     ad[2 * p] = pada;
            va[2 * p + 1] = 0.0f; ad[2 * p + 1] = pada;
        }
    }

    // ---- hoisted remote addresses ----------------------------------------
    uint32_t rab[NCTA];   // peer p's sbuf slot for my row (buffer 0)
    uint32_t la0 = sb_a + (uint32_t)(grow * 4);
#pragma unroll
    for (int p = 0; p < NCTA; p++) {
        asm("mapa.shared::cluster.u32 %0, %1, %2;" : "=r"(rab[p]) : "r"(la0), "r"(p));
    }
    uint32_t raA = 0, raB = 0;  // peer tid's mbar[0], mbar[1] (tid<NCTA)
    if (tid < NCTA) {
        asm("mapa.shared::cluster.u32 %0, %1, %2;" : "=r"(raA) : "r"(mb_a), "r"(tid));
        raB = raA + 8;
    }

    float u_next = __ldg(&d_U[grow]);  // U for t=0

    for (int t = 0; t < T_STEPS; t++) {
        float u = u_next;

        float a0 = 0, a1 = 0, a2 = 0, a3 = 0, a4 = 0, a5 = 0, a6 = 0, a7 = 0;
        float s;
        if (!(t & 1)) {
            // read buf0 ([ad]), write buf1 ([rab]+4096)
#pragma unroll
            for (int e = 0; e < 2 * KREG; e += 8) {
                float x0, x1, x2, x3, x4, x5, x6, x7;
                asm volatile("ld.shared.f32 %0, [%1];" : "=f"(x0) : "r"(ad[e + 0]));
                asm volatile("ld.shared.f32 %0, [%1];" : "=f"(x1) : "r"(ad[e + 1]));
                asm volatile("ld.shared.f32 %0, [%1];" : "=f"(x2) : "r"(ad[e + 2]));
                asm volatile("ld.shared.f32 %0, [%1];" : "=f"(x3) : "r"(ad[e + 3]));
                asm volatile("ld.shared.f32 %0, [%1];" : "=f"(x4) : "r"(ad[e + 4]));
                asm volatile("ld.shared.f32 %0, [%1];" : "=f"(x5) : "r"(ad[e + 5]));
                asm volatile("ld.shared.f32 %0, [%1];" : "=f"(x6) : "r"(ad[e + 6]));
                asm volatile("ld.shared.f32 %0, [%1];" : "=f"(x7) : "r"(ad[e + 7]));
                a0 += va[e + 0] * x0; a1 += va[e + 1] * x1;
                a2 += va[e + 2] * x2; a3 += va[e + 3] * x3;
                a4 += va[e + 4] * x4; a5 += va[e + 5] * x5;
                a6 += va[e + 6] * x6; a7 += va[e + 7] * x7;
            }
            for (int p = KREG; p < Kp; p++) {  // remainder pairs from smem
                float2 v = srv[p - KREG][tid];
                unsigned c = src_[p - KREG][tid];
                a0 += v.x * sbuf[(c & 0xFFFFu) >> 2];
                a1 += v.y * sbuf[(c >> 16) >> 2];
            }
            float y = u + (((a0 + a1) + (a2 + a3)) + ((a4 + a5) + (a6 + a7)));
            float e2 = __expf(2.0f * y);
            s = 1.0f - __fdividef(2.0f, e2 + 1.0f);
#pragma unroll
            for (int p = 0; p < NCTA; p++)
                asm volatile("st.shared::cluster.f32 [%0+4096], %1;" :: "r"(rab[p]), "f"(s));
        } else {
            // read buf1 ([ad]+4096), write buf0 ([rab])
#pragma unroll
            for (int e = 0; e < 2 * KREG; e += 8) {
                float x0, x1, x2, x3, x4, x5, x6, x7;
                asm volatile("ld.shared.f32 %0, [%1+4096];" : "=f"(x0) : "r"(ad[e + 0]));
                asm volatile("ld.shared.f32 %0, [%1+4096];" : "=f"(x1) : "r"(ad[e + 1]));
                asm volatile("ld.shared.f32 %0, [%1+4096];" : "=f"(x2) : "r"(ad[e + 2]));
                asm volatile("ld.shared.f32 %0, [%1+4096];" : "=f"(x3) : "r"(ad[e + 3]));
                asm volatile("ld.shared.f32 %0, [%1+4096];" : "=f"(x4) : "r"(ad[e + 4]));
                asm volatile("ld.shared.f32 %0, [%1+4096];" : "=f"(x5) : "r"(ad[e + 5]));
                asm volatile("ld.shared.f32 %0, [%1+4096];" : "=f"(x6) : "r"(ad[e + 6]));
                asm volatile("ld.shared.f32 %0, [%1+4096];" : "=f"(x7) : "r"(ad[e + 7]));
                a0 += va[e + 0] * x0; a1 += va[e + 1] * x1;
                a2 += va[e + 2] * x2; a3 += va[e + 3] * x3;
                a4 += va[e + 4] * x4; a5 += va[e + 5] * x5;
                a6 += va[e + 6] * x6; a7 += va[e + 7] * x7;
            }
            for (int p = KREG; p < Kp; p++) {  // remainder pairs from smem
                float2 v = srv[p - KREG][tid];
                unsigned c = src_[p - KREG][tid];
                a0 += v.x * sbuf[R_DIM + ((c & 0xFFFFu) >> 2)];
                a1 += v.y * sbuf[R_DIM + ((c >> 16) >> 2)];
            }
            float y = u + (((a0 + a1) + (a2 + a3)) + ((a4 + a5) + (a6 + a7)));
            float e2 = __expf(2.0f * y);
            s = 1.0f - __fdividef(2.0f, e2 + 1.0f);
#pragma unroll
            for (int p = 0; p < NCTA; p++)
                asm volatile("st.shared::cluster.f32 [%0], %1;" :: "r"(rab[p]), "f"(s));
        }

        __syncthreads();  // all this CTA's stores + state reads done (R7 semantics)

        if (tid < NCTA) {
            // distributed plain cluster arrive (R7 kind): thread p -> peer p
            uint32_t ra = (t & 1) ? raB : raA;
            asm volatile("mbarrier.arrive.shared::cluster.b64 _, [%0];" :: "r"(ra) : "memory");
        }

        // ---- wait-shadow work: off the critical path --------------------
        out[(size_t)t * R_DIM + grow] = s;
        int tn = (t + 1 < T_STEPS) ? (t + 1) : t;
        u_next = __ldg(&d_U[(size_t)tn * R_DIM + grow]);

        uint32_t mba = mb_a + (uint32_t)((t & 1) * 8);
        unsigned parity = (t >> 1) & 1;  // each mbar flips every 2 steps
        asm volatile(
            "{ .reg .pred P;\n"
            "W%=:\n"
            " mbarrier.try_wait.parity.acquire.cluster.shared::cta.b64 P, [%0], %1, 0x989680;\n"
            " @!P bra W%=;\n"
            "}" :: "r"(mba), "r"(parity) : "memory");
    }
}

// ---------------------------------------------------------------------------
extern "C" void kernel_launch(void* const* d_in, const int* in_sizes, int n_in,
                              void* d_out, int out_size) {
    const float* X    = (const float*)d_in[0];  // (T, I)
    const float* Win  = (const float*)d_in[1];  // (R, I)
    const float* Wres = (const float*)d_in[2];  // (R, R)
    const float* s0   = (const float*)d_in[3];  // (R,)
    float* out = (float*)d_out;                 // (T, R)

    cudaFuncSetAttribute(k_prep, cudaFuncAttributeMaxDynamicSharedMemorySize, B2_SMEM);

    k_prep<<<PREP_BLOCKS, 256, B2_SMEM>>>(Wres, X, Win);

    cudaLaunchConfig_t cfg = {};
    cfg.gridDim = {NCTA, 1, 1};
    cfg.blockDim = {RPC, 1, 1};
    cfg.dynamicSmemBytes = 0;
    cudaLaunchAttribute attrs[1];
    attrs[0].id = cudaLaunchAttributeClusterDimension;
    attrs[0].val.clusterDim = {NCTA, 1, 1};
    cfg.attrs = attrs;
    cfg.numAttrs = 1;
    cudaLaunchKernelEx(&cfg, k_esn, (const float*)s0, (float*)out);
}

// round 13
// speedup vs baseline: 1.2934x; 1.2934x over previous
#include <cuda_runtime.h>
#include <cstdint>

// ESN: s_t = tanh(U_t + W_res @ s_{t-1}),  U = X @ W_in^T
// T=16384 steps, R=1024 reservoir, I=128 input. W_res ~5% dense.
//
// R12 = R7 (8.66ms, twice-proven) with EXACTLY ONE change: KREG 40 -> 36
// (72-element register gather; slot distribution says Kp<=36 almost always,
// so the smem remainder path stays cold). R11's regression is attributed to
// its wait-shadow move (shortened U-prefetch cover), which is NOT repeated:
// loop body, store order, prefetch placement, and sync are R7-verbatim.

#define T_STEPS 16384
#define R_DIM   1024
#define I_DIM   128
#define NCTA    8
#define RPC     128     // rows per CTA == threads per CTA
#define ELLCAP  192     // max slots per row (global build clamp)
#define KREG    36      // pairs held in registers per thread
#define SREM    28      // extra pairs staged in smem (KREG+SREM = 64 = clamp)

__device__ float    d_U[(size_t)T_STEPS * R_DIM];        // 64 MiB
__device__ float2   d_ellv2[(ELLCAP / 2) * R_DIM];       // pair-packed vals
__device__ unsigned d_ellc2[(ELLCAP / 2) * R_DIM];       // pair-packed BYTE offsets (2xu16)
__device__ int      d_kgrp[R_DIM / 32];                  // slots per 32-row group (even)

__device__ __forceinline__ uint32_t smaddr(const void* p) {
    uint32_t a;
    asm("{ .reg .u64 t; cvta.to.shared.u64 t, %1; cvt.u32.u64 %0, t; }"
        : "=r"(a) : "l"(p));
    return a;
}

// ---------------------------------------------------------------------------
// Fused prep kernel: blocks [0,32) build the bank-conflict-free ELL schedule
// (one warp per 32-row group); blocks [32, 32+4096) compute U = X @ W_in^T.
#define B2_BCOL 0
#define B2_BVAL (32 * 32 * 16 * 2)
#define B2_BCNT (B2_BVAL + 32 * 32 * 16 * 4)
#define B2_MASK (B2_BCNT + 32 * 32 * 4)
#define B2_SMEM (B2_MASK + 32 * 4)
#define GEMM_TILES_T (T_STEPS / 64)
#define GEMM_TILES_R (R_DIM / 64)
#define PREP_BLOCKS (32 + GEMM_TILES_T * GEMM_TILES_R)

__global__ __launch_bounds__(256) void k_prep(const float* __restrict__ W,
                                              const float* __restrict__ X,
                                              const float* __restrict__ Win) {
    if (blockIdx.x < 32) {
        if (threadIdx.x >= 32) return;
        extern __shared__ unsigned char sm[];
        unsigned short* bcol    = (unsigned short*)(sm + B2_BCOL);  // [r][b][16]
        float*          bval    = (float*)(sm + B2_BVAL);           // [r][b][16]
        int*            bcnt    = (int*)(sm + B2_BCNT);             // [r][b]
        unsigned*       rowmask = (unsigned*)(sm + B2_MASK);        // [r]

        int g = blockIdx.x;
        int r = threadIdx.x;  // 0..31

        for (int b = 0; b < 32; b++) bcnt[r * 32 + b] = 0;
        const float4* Wr4 = (const float4*)(W + (size_t)(g * 32 + r) * R_DIM);
        for (int c4 = 0; c4 < R_DIM / 4; c4++) {
            float4 w4 = Wr4[c4];
            float wv[4] = {w4.x, w4.y, w4.z, w4.w};
#pragma unroll
            for (int j = 0; j < 4; j++) {
                float w = wv[j];
                if (w != 0.0f) {
                    int c = c4 * 4 + j;
                    int b = c & 31;
                    int i = bcnt[r * 32 + b]++;
                    if (i < 16) {
                        bcol[(r * 32 + b) * 16 + i] = (unsigned short)c;
                        bval[(r * 32 + b) * 16 + i] = w;
                    }
                }
            }
        }
        unsigned m = 0;
        for (int b = 0; b < 32; b++)
            if (bcnt[r * 32 + b] > 0) m |= 1u << b;
        rowmask[r] = m;
        __syncwarp();

        if (r == 0) {
            int rows_left = 0;
            for (int i = 0; i < 32; i++)
                if (rowmask[i]) rows_left++;
            int s = 0;
            while (rows_left > 0 && s < ELLCAP) {
                unsigned used = 0, pickedmask = 0;
                for (int i = 0; i < 32; i++) {
                    int rr = (s + i) & 31;
                    unsigned avail = rowmask[rr] & ~used;
                    if (avail) {
                        int b = __ffs(avail) - 1;
                        int c = --bcnt[rr * 32 + b];
                        unsigned short col = bcol[(rr * 32 + b) * 16 + c];
                        float v = bval[(rr * 32 + b) * 16 + c];
                        if (c == 0) {
                            rowmask[rr] &= ~(1u << b);
                            if (!rowmask[rr]) rows_left--;
                        }
                        used |= 1u << b;
                        pickedmask |= 1u << rr;
                        size_t idx = (size_t)(s >> 1) * R_DIM + g * 32 + rr;
                        ((float*)d_ellv2)[idx * 2 + (s & 1)] = v;
                        ((unsigned short*)d_ellc2)[idx * 2 + (s & 1)] =
                            (unsigned short)(col * 4);  // BYTE offset
                    }
                }
                unsigned freeb = ~used;
                for (int rr = 0; rr < 32; rr++) {
                    if (!((pickedmask >> rr) & 1)) {
                        int b = __ffs(freeb) - 1;
                        freeb &= freeb - 1;
                        size_t idx = (size_t)(s >> 1) * R_DIM + g * 32 + rr;
                        ((float*)d_ellv2)[idx * 2 + (s & 1)] = 0.0f;
                        ((unsigned short*)d_ellc2)[idx * 2 + (s & 1)] =
                            (unsigned short)(b * 4);
                    }
                }
                s++;
            }
            if (s & 1) {  // pad to even slot count; pads bank-distinct
                for (int rr = 0; rr < 32; rr++) {
                    size_t idx = (size_t)(s >> 1) * R_DIM + g * 32 + rr;
                    ((float*)d_ellv2)[idx * 2 + 1] = 0.0f;
                    ((unsigned short*)d_ellc2)[idx * 2 + 1] = (unsigned short)(rr * 4);
                }
                s++;
            }
            d_kgrp[g] = s;
        }
        return;
    }

    // ---------------- gemm path: U = X @ W_in^T, 64x64 tiles ---------------
    __shared__ float xs[64][68];
    __shared__ float ws[64][68];
    int gb = blockIdx.x - 32;
    int bt = (gb % GEMM_TILES_T) * 64;
    int br = (gb / GEMM_TILES_T) * 64;
    int ty = threadIdx.x >> 4;
    int tx = threadIdx.x & 15;

    float acc[4][4];
#pragma unroll
    for (int i = 0; i < 4; i++)
#pragma unroll
        for (int j = 0; j < 4; j++) acc[i][j] = 0.0f;

    for (int kc = 0; kc < I_DIM; kc += 64) {
        for (int i = threadIdx.x; i < 64 * 16; i += 256) {
            int rr = i >> 4, cc = i & 15;
            *(float4*)&xs[rr][cc * 4] = *(const float4*)&X[(size_t)(bt + rr) * I_DIM + kc + cc * 4];
            *(float4*)&ws[rr][cc * 4] = *(const float4*)&Win[(size_t)(br + rr) * I_DIM + kc + cc * 4];
        }
        __syncthreads();
#pragma unroll
        for (int k = 0; k < 64; k++) {
            float a[4], b[4];
#pragma unroll
            for (int i = 0; i < 4; i++) a[i] = xs[ty + 16 * i][k];
#pragma unroll
            for (int j = 0; j < 4; j++) b[j] = ws[tx + 16 * j][k];
#pragma unroll
            for (int i = 0; i < 4; i++)
#pragma unroll
                for (int j = 0; j < 4; j++) acc[i][j] += a[i] * b[j];
        }
        __syncthreads();
    }
#pragma unroll
    for (int i = 0; i < 4; i++)
#pragma unroll
        for (int j = 0; j < 4; j++)
            d_U[(size_t)(bt + ty + 16 * i) * R_DIM + br + tx + 16 * j] = acc[i][j];
}

// ---------------------------------------------------------------------------
// Recurrence: 8-CTA cluster, 128 threads (4 warps), one FULL row per thread.
// R7-verbatim loop body; only KREG differs.
__global__ __launch_bounds__(RPC, 1)
void k_esn(const float* __restrict__ state0, float* __restrict__ out) {
    __shared__ float    sbuf[2 * R_DIM];          // double-buffered full state
    __shared__ float2   srv[SREM][RPC];           // remainder pairs (vals)
    __shared__ unsigned src_[SREM][RPC];          // remainder pairs (byte-off pairs)
    __shared__ unsigned long long mbar[2];
    __shared__ int kg_s[4];

    int tid = threadIdx.x;          // 0..127
    int cta = blockIdx.x;           // == cluster rank
    int grow = cta * RPC + tid;     // global row owned by this thread

    uint32_t sb_a = smaddr(sbuf);
    uint32_t mb_a = smaddr(mbar);

    if (tid < 4) {
        int v = d_kgrp[cta * 4 + tid];
        kg_s[tid] = (v > 2 * (KREG + SREM)) ? 2 * (KREG + SREM) : v;
    }
    if (tid == 0) {
        // 8 arrivals per phase barrier: one per source CTA
        asm volatile("mbarrier.init.shared.b64 [%0], %1;" :: "r"(mb_a), "r"(NCTA));
        asm volatile("mbarrier.init.shared.b64 [%0], %1;" :: "r"(mb_a + 8), "r"(NCTA));
    }
    for (int i = tid; i < R_DIM; i += RPC) sbuf[i] = state0[i];
    __syncthreads();

    // stage remainder pairs [KREG, Kp) into smem
    for (int idx = tid; idx < SREM * RPC; idx += RPC) {
        int p = KREG + idx / RPC, lr = idx % RPC;
        int kp2 = kg_s[lr >> 5] >> 1;
        if (p < kp2) {
            srv[p - KREG][lr] = d_ellv2[(size_t)p * R_DIM + cta * RPC + lr];
            src_[p - KREG][lr] = d_ellc2[(size_t)p * R_DIM + cta * RPC + lr];
        }
    }
    __syncthreads();

    // all CTAs' mbarrier.init + initial state complete before use
    asm volatile("barrier.cluster.arrive.aligned;" ::: "memory");
    asm volatile("barrier.cluster.wait.aligned;" ::: "memory");

    int Kp = kg_s[tid >> 5] >> 1;   // pair count for my row's group

    // ---- preload: values + ABSOLUTE smem addresses (buffer 0) ------------
    float    va[2 * KREG];
    uint32_t ad[2 * KREG];
    uint32_t pada = sb_a + (uint32_t)((tid & 31) * 4);  // lane-distinct pad bank
#pragma unroll
    for (int p = 0; p < KREG; p++) {
        if (p < Kp) {
            float2 v = d_ellv2[(size_t)p * R_DIM + grow];
            unsigned c = d_ellc2[(size_t)p * R_DIM + grow];
            va[2 * p] = v.x;     ad[2 * p] = sb_a + (c & 0xFFFFu);
            va[2 * p + 1] = v.y; ad[2 * p + 1] = sb_a + (c >> 16);
        } else {
            va[2 * p] = 0.0f;     ad[2 * p] = pada;
            va[2 * p + 1] = 0.0f; ad[2 * p + 1] = pada;
        }
    }

    // ---- hoisted remote addresses ----------------------------------------
    uint32_t rab[NCTA];   // peer p's sbuf slot for my row (buffer 0)
    uint32_t la0 = sb_a + (uint32_t)(grow * 4);
#pragma unroll
    for (int p = 0; p < NCTA; p++) {
        asm("mapa.shared::cluster.u32 %0, %1, %2;" : "=r"(rab[p]) : "r"(la0), "r"(p));
    }
    uint32_t raA = 0, raB = 0;  // peer tid's mbar[0], mbar[1] (tid<NCTA)
    if (tid < NCTA) {
        asm("mapa.shared::cluster.u32 %0, %1, %2;" : "=r"(raA) : "r"(mb_a), "r"(tid));
        raB = raA + 8;
    }

    float u_next = __ldg(&d_U[grow]);  // U for t=0

    for (int t = 0; t < T_STEPS; t++) {
        float u = u_next;
        int tn = (t + 1 < T_STEPS) ? (t + 1) : t;
        u_next = __ldg(&d_U[(size_t)tn * R_DIM + grow]);  // full-step cover

        float a0 = 0, a1 = 0, a2 = 0, a3 = 0, a4 = 0, a5 = 0, a6 = 0, a7 = 0;
        float s;
        if (!(t & 1)) {
            // read buf0 ([ad]), write buf1 ([rab]+4096)
#pragma unroll
            for (int e = 0; e < 2 * KREG; e += 8) {
                float x0, x1, x2, x3, x4, x5, x6, x7;
                asm volatile("ld.shared.f32 %0, [%1];" : "=f"(x0) : "r"(ad[e + 0]));
                asm volatile("ld.shared.f32 %0, [%1];" : "=f"(x1) : "r"(ad[e + 1]));
                asm volatile("ld.shared.f32 %0, [%1];" : "=f"(x2) : "r"(ad[e + 2]));
                asm volatile("ld.shared.f32 %0, [%1];" : "=f"(x3) : "r"(ad[e + 3]));
                asm volatile("ld.shared.f32 %0, [%1];" : "=f"(x4) : "r"(ad[e + 4]));
                asm volatile("ld.shared.f32 %0, [%1];" : "=f"(x5) : "r"(ad[e + 5]));
                asm volatile("ld.shared.f32 %0, [%1];" : "=f"(x6) : "r"(ad[e + 6]));
                asm volatile("ld.shared.f32 %0, [%1];" : "=f"(x7) : "r"(ad[e + 7]));
                a0 += va[e + 0] * x0; a1 += va[e + 1] * x1;
                a2 += va[e + 2] * x2; a3 += va[e + 3] * x3;
                a4 += va[e + 4] * x4; a5 += va[e + 5] * x5;
                a6 += va[e + 6] * x6; a7 += va[e + 7] * x7;
            }
            for (int p = KREG; p < Kp; p++) {  // remainder pairs (cold)
                float2 v = srv[p - KREG][tid];
                unsigned c = src_[p - KREG][tid];
                a0 += v.x * sbuf[(c & 0xFFFFu) >> 2];
                a1 += v.y * sbuf[(c >> 16) >> 2];
            }
            float y = u + (((a0 + a1) + (a2 + a3)) + ((a4 + a5) + (a6 + a7)));
            float e2 = __expf(2.0f * y);
            s = 1.0f - __fdividef(2.0f, e2 + 1.0f);
#pragma unroll
            for (int p = 0; p < NCTA; p++)
                asm volatile("st.shared::cluster.f32 [%0+4096], %1;" :: "r"(rab[p]), "f"(s));
        } else {
            // read buf1 ([ad]+4096), write buf0 ([rab])
#pragma unroll
            for (int e = 0; e < 2 * KREG; e += 8) {
                float x0, x1, x2, x3, x4, x5, x6, x7;
                asm volatile("ld.shared.f32 %0, [%1+4096];" : "=f"(x0) : "r"(ad[e + 0]));
                asm volatile("ld.shared.f32 %0, [%1+4096];" : "=f"(x1) : "r"(ad[e + 1]));
                asm volatile("ld.shared.f32 %0, [%1+4096];" : "=f"(x2) : "r"(ad[e + 2]));
                asm volatile("ld.shared.f32 %0, [%1+4096];" : "=f"(x3) : "r"(ad[e + 3]));
                asm volatile("ld.shared.f32 %0, [%1+4096];" : "=f"(x4) : "r"(ad[e + 4]));
                asm volatile("ld.shared.f32 %0, [%1+4096];" : "=f"(x5) : "r"(ad[e + 5]));
                asm volatile("ld.shared.f32 %0, [%1+4096];" : "=f"(x6) : "r"(ad[e + 6]));
                asm volatile("ld.shared.f32 %0, [%1+4096];" : "=f"(x7) : "r"(ad[e + 7]));
                a0 += va[e + 0] * x0; a1 += va[e + 1] * x1;
                a2 += va[e + 2] * x2; a3 += va[e + 3] * x3;
                a4 += va[e + 4] * x4; a5 += va[e + 5] * x5;
                a6 += va[e + 6] * x6; a7 += va[e + 7] * x7;
            }
            for (int p = KREG; p < Kp; p++) {  // remainder pairs (cold)
                float2 v = srv[p - KREG][tid];
                unsigned c = src_[p - KREG][tid];
                a0 += v.x * sbuf[R_DIM + ((c & 0xFFFFu) >> 2)];
                a1 += v.y * sbuf[R_DIM + ((c >> 16) >> 2)];
            }
            float y = u + (((a0 + a1) + (a2 + a3)) + ((a4 + a5) + (a6 + a7)));
            float e2 = __expf(2.0f * y);
            s = 1.0f - __fdividef(2.0f, e2 + 1.0f);
#pragma unroll
            for (int p = 0; p < NCTA; p++)
                asm volatile("st.shared::cluster.f32 [%0], %1;" :: "r"(rab[p]), "f"(s));
        }
        out[(size_t)t * R_DIM + grow] = s;

        __syncthreads();  // all this CTA's stores + state reads done (R7 semantics)

        if (tid < NCTA) {
            // distributed plain cluster arrive (R7 kind): thread p -> peer p
            uint32_t ra = (t & 1) ? raB : raA;
            asm volatile("mbarrier.arrive.shared::cluster.b64 _, [%0];" :: "r"(ra) : "memory");
        }
        uint32_t mba = mb_a + (uint32_t)((t & 1) * 8);
        unsigned parity = (t >> 1) & 1;  // each mbar flips every 2 steps
        asm volatile(
            "{ .reg .pred P;\n"
            "W%=:\n"
            " mbarrier.try_wait.parity.acquire.cluster.shared::cta.b64 P, [%0], %1, 0x989680;\n"
            " @!P bra W%=;\n"
            "}" :: "r"(mba), "r"(parity) : "memory");
    }
}

// ---------------------------------------------------------------------------
extern "C" void kernel_launch(void* const* d_in, const int* in_sizes, int n_in,
                              void* d_out, int out_size) {
    const float* X    = (const float*)d_in[0];  // (T, I)
    const float* Win  = (const float*)d_in[1];  // (R, I)
    const float* Wres = (const float*)d_in[2];  // (R, R)
    const float* s0   = (const float*)d_in[3];  // (R,)
    float* out = (float*)d_out;                 // (T, R)

    cudaFuncSetAttribute(k_prep, cudaFuncAttributeMaxDynamicSharedMemorySize, B2_SMEM);

    k_prep<<<PREP_BLOCKS, 256, B2_SMEM>>>(Wres, X, Win);

    cudaLaunchConfig_t cfg = {};
    cfg.gridDim = {NCTA, 1, 1};
    cfg.blockDim = {RPC, 1, 1};
    cfg.dynamicSmemBytes = 0;
    cudaLaunchAttribute attrs[1];
    attrs[0].id = cudaLaunchAttributeClusterDimension;
    attrs[0].val.clusterDim = {NCTA, 1, 1};
    cfg.attrs = attrs;
    cfg.numAttrs = 1;
    cudaLaunchKernelEx(&cfg, k_esn, (const float*)s0, (float*)out);
}

// round 14
// speedup vs baseline: 1.4521x; 1.1227x over previous
#include <cuda_runtime.h>
#include <cstdint>

// ESN: s_t = tanh(U_t + W_res @ s_{t-1}),  U = X @ W_in^T
// T=16384 steps, R=1024 reservoir, I=128 input. W_res ~5% dense.
//
// R13 = R7's k_esn VERBATIM (8.66ms, twice-proven; R8/R11/R12 proved every
// loop-body perturbation regresses — step time is a lockstep MAX and KREG=40
// covers max group Kp) + ONE change in k_prep's build path:
//   phase-1 bucket scratch had 32-way bank conflicts on every RMW
//   (strides multiple of 32 banks across lanes). Padded strides:
//   bcnt 33 ints/row, bval 513 floats/row, bcol 514 u16/row -> conflict-free.
//   ELL OUTPUT IS BIT-IDENTICAL; only scratch layout changes.

#define T_STEPS 16384
#define R_DIM   1024
#define I_DIM   128
#define NCTA    8
#define RPC     128     // rows per CTA == threads per CTA
#define ELLCAP  192     // max slots per row (global build clamp)
#define KREG    40      // pairs held in registers per thread (covers max Kp)
#define SREM    24      // extra pairs staged in smem (KREG+SREM = 64 = clamp)

__device__ float    d_U[(size_t)T_STEPS * R_DIM];        // 64 MiB
__device__ float2   d_ellv2[(ELLCAP / 2) * R_DIM];       // pair-packed vals
__device__ unsigned d_ellc2[(ELLCAP / 2) * R_DIM];       // pair-packed BYTE offsets (2xu16)
__device__ int      d_kgrp[R_DIM / 32];                  // slots per 32-row group (even)

__device__ __forceinline__ uint32_t smaddr(const void* p) {
    uint32_t a;
    asm("{ .reg .u64 t; cvta.to.shared.u64 t, %1; cvt.u32.u64 %0, t; }"
        : "=r"(a) : "l"(p));
    return a;
}

// ---------------------------------------------------------------------------
// Fused prep kernel: blocks [0,32) build the bank-conflict-free ELL schedule
// (one warp per 32-row group); blocks [32, 32+4096) compute U = X @ W_in^T.
// Scratch layout padded for conflict-free phase-1 bucketing:
//   bcol: u16, row stride 514  (byte stride 1028; /4 mod 32 = 1)
//   bval: f32, row stride 513  (byte stride 2052; /4 mod 32 = 1)
//   bcnt: int, row stride 33
#define BCOL_STRIDE 514
#define BVAL_STRIDE 513
#define BCNT_STRIDE 33
#define B2_BCOL 0
#define B2_BVAL (32 * BCOL_STRIDE * 2)                        // 32896
#define B2_BCNT (B2_BVAL + 32 * BVAL_STRIDE * 4)              // 98560
#define B2_MASK (B2_BCNT + 32 * BCNT_STRIDE * 4)              // 102784
#define B2_SMEM (B2_MASK + 32 * 4)                            // 102912
#define GEMM_TILES_T (T_STEPS / 64)
#define GEMM_TILES_R (R_DIM / 64)
#define PREP_BLOCKS (32 + GEMM_TILES_T * GEMM_TILES_R)

__global__ __launch_bounds__(256) void k_prep(const float* __restrict__ W,
                                              const float* __restrict__ X,
                                              const float* __restrict__ Win) {
    if (blockIdx.x < 32) {
        if (threadIdx.x >= 32) return;
        extern __shared__ unsigned char sm[];
        unsigned short* bcol    = (unsigned short*)(sm + B2_BCOL);  // [r][b][16], stride 514
        float*          bval    = (float*)(sm + B2_BVAL);           // [r][b][16], stride 513
        int*            bcnt    = (int*)(sm + B2_BCNT);             // [r][b], stride 33
        unsigned*       rowmask = (unsigned*)(sm + B2_MASK);        // [r]

        int g = blockIdx.x;
        int r = threadIdx.x;  // 0..31 (lane = local row)

        for (int b = 0; b < 32; b++) bcnt[r * BCNT_STRIDE + b] = 0;
        const float4* Wr4 = (const float4*)(W + (size_t)(g * 32 + r) * R_DIM);
        for (int c4 = 0; c4 < R_DIM / 4; c4++) {
            float4 w4 = Wr4[c4];
            float wv[4] = {w4.x, w4.y, w4.z, w4.w};
#pragma unroll
            for (int j = 0; j < 4; j++) {
                float w = wv[j];
                if (w != 0.0f) {
                    int c = c4 * 4 + j;
                    int b = c & 31;
                    int i = bcnt[r * BCNT_STRIDE + b]++;
                    if (i < 16) {
                        bcol[r * BCOL_STRIDE + b * 16 + i] = (unsigned short)c;
                        bval[r * BVAL_STRIDE + b * 16 + i] = w;
                    }
                }
            }
        }
        unsigned m = 0;
        for (int b = 0; b < 32; b++)
            if (bcnt[r * BCNT_STRIDE + b] > 0) m |= 1u << b;
        rowmask[r] = m;
        __syncwarp();

        if (r == 0) {
            int rows_left = 0;
            for (int i = 0; i < 32; i++)
                if (rowmask[i]) rows_left++;
            int s = 0;
            while (rows_left > 0 && s < ELLCAP) {
                unsigned used = 0, pickedmask = 0;
                for (int i = 0; i < 32; i++) {
                    int rr = (s + i) & 31;
                    unsigned avail = rowmask[rr] & ~used;
                    if (avail) {
                        int b = __ffs(avail) - 1;
                        int c = --bcnt[rr * BCNT_STRIDE + b];
                        unsigned short col = bcol[rr * BCOL_STRIDE + b * 16 + c];
                        float v = bval[rr * BVAL_STRIDE + b * 16 + c];
                        if (c == 0) {
                            rowmask[rr] &= ~(1u << b);
                            if (!rowmask[rr]) rows_left--;
                        }
                        used |= 1u << b;
                        pickedmask |= 1u << rr;
                        size_t idx = (size_t)(s >> 1) * R_DIM + g * 32 + rr;
                        ((float*)d_ellv2)[idx * 2 + (s & 1)] = v;
                        ((unsigned short*)d_ellc2)[idx * 2 + (s & 1)] =
                            (unsigned short)(col * 4);  // BYTE offset
                    }
                }
                unsigned freeb = ~used;
                for (int rr = 0; rr < 32; rr++) {
                    if (!((pickedmask >> rr) & 1)) {
                        int b = __ffs(freeb) - 1;
                        freeb &= freeb - 1;
                        size_t idx = (size_t)(s >> 1) * R_DIM + g * 32 + rr;
                        ((float*)d_ellv2)[idx * 2 + (s & 1)] = 0.0f;
                        ((unsigned short*)d_ellc2)[idx * 2 + (s & 1)] =
                            (unsigned short)(b * 4);
                    }
                }
                s++;
            }
            if (s & 1) {  // pad to even slot count; pads bank-distinct
                for (int rr = 0; rr < 32; rr++) {
                    size_t idx = (size_t)(s >> 1) * R_DIM + g * 32 + rr;
                    ((float*)d_ellv2)[idx * 2 + 1] = 0.0f;
                    ((unsigned short*)d_ellc2)[idx * 2 + 1] = (unsigned short)(rr * 4);
                }
                s++;
            }
            d_kgrp[g] = s;
        }
        return;
    }

    // ---------------- gemm path: U = X @ W_in^T, 64x64 tiles ---------------
    __shared__ float xs[64][68];
    __shared__ float ws[64][68];
    int gb = blockIdx.x - 32;
    int bt = (gb % GEMM_TILES_T) * 64;
    int br = (gb / GEMM_TILES_T) * 64;
    int ty = threadIdx.x >> 4;
    int tx = threadIdx.x & 15;

    float acc[4][4];
#pragma unroll
    for (int i = 0; i < 4; i++)
#pragma unroll
        for (int j = 0; j < 4; j++) acc[i][j] = 0.0f;

    for (int kc = 0; kc < I_DIM; kc += 64) {
        for (int i = threadIdx.x; i < 64 * 16; i += 256) {
            int rr = i >> 4, cc = i & 15;
            *(float4*)&xs[rr][cc * 4] = *(const float4*)&X[(size_t)(bt + rr) * I_DIM + kc + cc * 4];
            *(float4*)&ws[rr][cc * 4] = *(const float4*)&Win[(size_t)(br + rr) * I_DIM + kc + cc * 4];
        }
        __syncthreads();
#pragma unroll
        for (int k = 0; k < 64; k++) {
            float a[4], b[4];
#pragma unroll
            for (int i = 0; i < 4; i++) a[i] = xs[ty + 16 * i][k];
#pragma unroll
            for (int j = 0; j < 4; j++) b[j] = ws[tx + 16 * j][k];
#pragma unroll
            for (int i = 0; i < 4; i++)
#pragma unroll
                for (int j = 0; j < 4; j++) acc[i][j] += a[i] * b[j];
        }
        __syncthreads();
    }
#pragma unroll
    for (int i = 0; i < 4; i++)
#pragma unroll
        for (int j = 0; j < 4; j++)
            d_U[(size_t)(bt + ty + 16 * i) * R_DIM + br + tx + 16 * j] = acc[i][j];
}

// ---------------------------------------------------------------------------
// Recurrence: 8-CTA cluster, 128 threads (4 warps), one FULL row per thread.
// R7 VERBATIM — do not touch (R8/R11/R12 all regressed on perturbations).
__global__ __launch_bounds__(RPC, 1)
void k_esn(const float* __restrict__ state0, float* __restrict__ out) {
    __shared__ float    sbuf[2 * R_DIM];          // double-buffered full state
    __shared__ float2   srv[SREM][RPC];           // remainder pairs (vals)
    __shared__ unsigned src_[SREM][RPC];          // remainder pairs (byte-off pairs)
    __shared__ unsigned long long mbar[2];
    __shared__ int kg_s[4];

    int tid = threadIdx.x;          // 0..127
    int cta = blockIdx.x;           // == cluster rank
    int grow = cta * RPC + tid;     // global row owned by this thread

    uint32_t sb_a = smaddr(sbuf);
    uint32_t mb_a = smaddr(mbar);

    if (tid < 4) {
        int v = d_kgrp[cta * 4 + tid];
        kg_s[tid] = (v > 2 * (KREG + SREM)) ? 2 * (KREG + SREM) : v;
    }
    if (tid == 0) {
        // 8 arrivals per phase barrier: one per source CTA
        asm volatile("mbarrier.init.shared.b64 [%0], %1;" :: "r"(mb_a), "r"(NCTA));
        asm volatile("mbarrier.init.shared.b64 [%0], %1;" :: "r"(mb_a + 8), "r"(NCTA));
    }
    for (int i = tid; i < R_DIM; i += RPC) sbuf[i] = state0[i];
    __syncthreads();

    // stage remainder pairs [KREG, Kp) into smem
    for (int idx = tid; idx < SREM * RPC; idx += RPC) {
        int p = KREG + idx / RPC, lr = idx % RPC;
        int kp2 = kg_s[lr >> 5] >> 1;
        if (p < kp2) {
            srv[p - KREG][lr] = d_ellv2[(size_t)p * R_DIM + cta * RPC + lr];
            src_[p - KREG][lr] = d_ellc2[(size_t)p * R_DIM + cta * RPC + lr];
        }
    }
    __syncthreads();

    // all CTAs' mbarrier.init + initial state complete before use
    asm volatile("barrier.cluster.arrive.aligned;" ::: "memory");
    asm volatile("barrier.cluster.wait.aligned;" ::: "memory");

    int Kp = kg_s[tid >> 5] >> 1;   // pair count for my row's group

    // ---- preload: values + ABSOLUTE smem addresses (buffer 0) ------------
    float    va[2 * KREG];
    uint32_t ad[2 * KREG];
    uint32_t pada = sb_a + (uint32_t)((tid & 31) * 4);  // lane-distinct pad bank
#pragma unroll
    for (int p = 0; p < KREG; p++) {
        if (p < Kp) {
            float2 v = d_ellv2[(size_t)p * R_DIM + grow];
            unsigned c = d_ellc2[(size_t)p * R_DIM + grow];
            va[2 * p] = v.x;     ad[2 * p] = sb_a + (c & 0xFFFFu);
            va[2 * p + 1] = v.y; ad[2 * p + 1] = sb_a + (c >> 16);
        } else {
            va[2 * p] = 0.0f;     ad[2 * p] = pada;
            va[2 * p + 1] = 0.0f; ad[2 * p + 1] = pada;
        }
    }

    // ---- hoisted remote addresses ----------------------------------------
    uint32_t rab[NCTA];   // peer p's sbuf slot for my row (buffer 0)
    uint32_t la0 = sb_a + (uint32_t)(grow * 4);
#pragma unroll
    for (int p = 0; p < NCTA; p++) {
        asm("mapa.shared::cluster.u32 %0, %1, %2;" : "=r"(rab[p]) : "r"(la0), "r"(p));
    }
    uint32_t raA = 0, raB = 0;  // peer tid's mbar[0], mbar[1] (tid<NCTA)
    if (tid < NCTA) {
        asm("mapa.shared::cluster.u32 %0, %1, %2;" : "=r"(raA) : "r"(mb_a), "r"(tid));
        raB = raA + 8;
    }

    float u_next = __ldg(&d_U[grow]);  // U for t=0

    for (int t = 0; t < T_STEPS; t++) {
        float u = u_next;
        int tn = (t + 1 < T_STEPS) ? (t + 1) : t;
        u_next = __ldg(&d_U[(size_t)tn * R_DIM + grow]);  // full-step cover

        float a0 = 0, a1 = 0, a2 = 0, a3 = 0, a4 = 0, a5 = 0, a6 = 0, a7 = 0;
        float s;
        if (!(t & 1)) {
            // read buf0 ([ad]), write buf1 ([rab]+4096)
#pragma unroll
            for (int e = 0; e < 2 * KREG; e += 8) {
                float x0, x1, x2, x3, x4, x5, x6, x7;
                asm volatile("ld.shared.f32 %0, [%1];" : "=f"(x0) : "r"(ad[e + 0]));
                asm volatile("ld.shared.f32 %0, [%1];" : "=f"(x1) : "r"(ad[e + 1]));
                asm volatile("ld.shared.f32 %0, [%1];" : "=f"(x2) : "r"(ad[e + 2]));
                asm volatile("ld.shared.f32 %0, [%1];" : "=f"(x3) : "r"(ad[e + 3]));
                asm volatile("ld.shared.f32 %0, [%1];" : "=f"(x4) : "r"(ad[e + 4]));
                asm volatile("ld.shared.f32 %0, [%1];" : "=f"(x5) : "r"(ad[e + 5]));
                asm volatile("ld.shared.f32 %0, [%1];" : "=f"(x6) : "r"(ad[e + 6]));
                asm volatile("ld.shared.f32 %0, [%1];" : "=f"(x7) : "r"(ad[e + 7]));
                a0 += va[e + 0] * x0; a1 += va[e + 1] * x1;
                a2 += va[e + 2] * x2; a3 += va[e + 3] * x3;
                a4 += va[e + 4] * x4; a5 += va[e + 5] * x5;
                a6 += va[e + 6] * x6; a7 += va[e + 7] * x7;
            }
            for (int p = KREG; p < Kp; p++) {  // remainder (cold at KREG=40)
                float2 v = srv[p - KREG][tid];
                unsigned c = src_[p - KREG][tid];
                a0 += v.x * sbuf[(c & 0xFFFFu) >> 2];
                a1 += v.y * sbuf[(c >> 16) >> 2];
            }
            float y = u + (((a0 + a1) + (a2 + a3)) + ((a4 + a5) + (a6 + a7)));
            float e2 = __expf(2.0f * y);
            s = 1.0f - __fdividef(2.0f, e2 + 1.0f);
#pragma unroll
            for (int p = 0; p < NCTA; p++)
                asm volatile("st.shared::cluster.f32 [%0+4096], %1;" :: "r"(rab[p]), "f"(s));
        } else {
            // read buf1 ([ad]+4096), write buf0 ([rab])
#pragma unroll
            for (int e = 0; e < 2 * KREG; e += 8) {
                float x0, x1, x2, x3, x4, x5, x6, x7;
                asm volatile("ld.shared.f32 %0, [%1+4096];" : "=f"(x0) : "r"(ad[e + 0]));
                asm volatile("ld.shared.f32 %0, [%1+4096];" : "=f"(x1) : "r"(ad[e + 1]));
                asm volatile("ld.shared.f32 %0, [%1+4096];" : "=f"(x2) : "r"(ad[e + 2]));
                asm volatile("ld.shared.f32 %0, [%1+4096];" : "=f"(x3) : "r"(ad[e + 3]));
                asm volatile("ld.shared.f32 %0, [%1+4096];" : "=f"(x4) : "r"(ad[e + 4]));
                asm volatile("ld.shared.f32 %0, [%1+4096];" : "=f"(x5) : "r"(ad[e + 5]));
                asm volatile("ld.shared.f32 %0, [%1+4096];" : "=f"(x6) : "r"(ad[e + 6]));
                asm volatile("ld.shared.f32 %0, [%1+4096];" : "=f"(x7) : "r"(ad[e + 7]));
                a0 += va[e + 0] * x0; a1 += va[e + 1] * x1;
                a2 += va[e + 2] * x2; a3 += va[e + 3] * x3;
                a4 += va[e + 4] * x4; a5 += va[e + 5] * x5;
                a6 += va[e + 6] * x6; a7 += va[e + 7] * x7;
            }
            for (int p = KREG; p < Kp; p++) {  // remainder (cold at KREG=40)
                float2 v = srv[p - KREG][tid];
                unsigned c = src_[p - KREG][tid];
                a0 += v.x * sbuf[R_DIM + ((c & 0xFFFFu) >> 2)];
                a1 += v.y * sbuf[R_DIM + ((c >> 16) >> 2)];
            }
            float y = u + (((a0 + a1) + (a2 + a3)) + ((a4 + a5) + (a6 + a7)));
            float e2 = __expf(2.0f * y);
            s = 1.0f - __fdividef(2.0f, e2 + 1.0f);
#pragma unroll
            for (int p = 0; p < NCTA; p++)
                asm volatile("st.shared::cluster.f32 [%0], %1;" :: "r"(rab[p]), "f"(s));
        }
        out[(size_t)t * R_DIM + grow] = s;

        __syncthreads();  // all this CTA's stores + state reads done

        if (tid < NCTA) {
            // distributed plain cluster arrive: thread p -> peer p
            uint32_t ra = (t & 1) ? raB : raA;
            asm volatile("mbarrier.arrive.shared::cluster.b64 _, [%0];" :: "r"(ra) : "memory");
        }
        uint32_t mba = mb_a + (uint32_t)((t & 1) * 8);
        unsigned parity = (t >> 1) & 1;  // each mbar flips every 2 steps
        asm volatile(
            "{ .reg .pred P;\n"
            "W%=:\n"
            " mbarrier.try_wait.parity.acquire.cluster.shared::cta.b64 P, [%0], %1, 0x989680;\n"
            " @!P bra W%=;\n"
            "}" :: "r"(mba), "r"(parity) : "memory");
    }
}

// ---------------------------------------------------------------------------
extern "C" void kernel_launch(void* const* d_in, const int* in_sizes, int n_in,
                              void* d_out, int out_size) {
    const float* X    = (const float*)d_in[0];  // (T, I)
    const float* Win  = (const float*)d_in[1];  // (R, I)
    const float* Wres = (const float*)d_in[2];  // (R, R)
    const float* s0   = (const float*)d_in[3];  // (R,)
    float* out = (float*)d_out;                 // (T, R)

    cudaFuncSetAttribute(k_prep, cudaFuncAttributeMaxDynamicSharedMemorySize, B2_SMEM);

    k_prep<<<PREP_BLOCKS, 256, B2_SMEM>>>(Wres, X, Win);

    cudaLaunchConfig_t cfg = {};
    cfg.gridDim = {NCTA, 1, 1};
    cfg.blockDim = {RPC, 1, 1};
    cfg.dynamicSmemBytes = 0;
    cudaLaunchAttribute attrs[1];
    attrs[0].id = cudaLaunchAttributeClusterDimension;
    attrs[0].val.clusterDim = {NCTA, 1, 1};
    cfg.attrs = attrs;
    cfg.numAttrs = 1;
    cudaLaunchKernelEx(&cfg, k_esn, (const float*)s0, (float*)out);
}

// round 15
// speedup vs baseline: 1.4974x; 1.0312x over previous
#include <cuda_runtime.h>
#include <cstdint>

// ESN: s_t = tanh(U_t + W_res @ s_{t-1}),  U = X @ W_in^T
// T=16384 steps, R=1024 reservoir, I=128 input. W_res ~5% dense.
//
// R14 = R7 VERBATIM (8.66ms, twice-proven; R8/R11/R12/R13 showed the loop
// body + launch structure are at their floor) with EXACTLY ONE change:
//   tanh via single-instruction tanh.approx.f32 (MUFU, ~16cyc) instead of
//   the exp-identity chain (~45cyc serial: MUL+EX2+ADD+RCP+MUL+ADD).
//   The tail sits on the critical path between last FFMA and first remote
//   store, so the saving is per-step. Accuracy: ~1e-5 abs error, recurrence
//   shows no amplification (tanh contraction, SR=0.9) -> est rel_err
//   1e-5..1e-4, well under the 1e-3 gate.

#define T_STEPS 16384
#define R_DIM   1024
#define I_DIM   128
#define NCTA    8
#define RPC     128     // rows per CTA == threads per CTA
#define ELLCAP  192     // max slots per row (global build clamp)
#define KREG    40      // pairs held in registers per thread (covers max Kp)
#define SREM    24      // extra pairs staged in smem (KREG+SREM = 64 = clamp)

__device__ float    d_U[(size_t)T_STEPS * R_DIM];        // 64 MiB
__device__ float2   d_ellv2[(ELLCAP / 2) * R_DIM];       // pair-packed vals
__device__ unsigned d_ellc2[(ELLCAP / 2) * R_DIM];       // pair-packed BYTE offsets (2xu16)
__device__ int      d_kgrp[R_DIM / 32];                  // slots per 32-row group (even)

__device__ __forceinline__ uint32_t smaddr(const void* p) {
    uint32_t a;
    asm("{ .reg .u64 t; cvta.to.shared.u64 t, %1; cvt.u32.u64 %0, t; }"
        : "=r"(a) : "l"(p));
    return a;
}

// ---------------------------------------------------------------------------
// Fused prep kernel: blocks [0,32) build the bank-conflict-free ELL schedule
// (one warp per 32-row group); blocks [32, 32+4096) compute U = X @ W_in^T.
#define B2_BCOL 0
#define B2_BVAL (32 * 32 * 16 * 2)
#define B2_BCNT (B2_BVAL + 32 * 32 * 16 * 4)
#define B2_MASK (B2_BCNT + 32 * 32 * 4)
#define B2_SMEM (B2_MASK + 32 * 4)
#define GEMM_TILES_T (T_STEPS / 64)
#define GEMM_TILES_R (R_DIM / 64)
#define PREP_BLOCKS (32 + GEMM_TILES_T * GEMM_TILES_R)

__global__ __launch_bounds__(256) void k_prep(const float* __restrict__ W,
                                              const float* __restrict__ X,
                                              const float* __restrict__ Win) {
    if (blockIdx.x < 32) {
        if (threadIdx.x >= 32) return;
        extern __shared__ unsigned char sm[];
        unsigned short* bcol    = (unsigned short*)(sm + B2_BCOL);  // [r][b][16]
        float*          bval    = (float*)(sm + B2_BVAL);           // [r][b][16]
        int*            bcnt    = (int*)(sm + B2_BCNT);             // [r][b]
        unsigned*       rowmask = (unsigned*)(sm + B2_MASK);        // [r]

        int g = blockIdx.x;
        int r = threadIdx.x;  // 0..31

        for (int b = 0; b < 32; b++) bcnt[r * 32 + b] = 0;
        const float4* Wr4 = (const float4*)(W + (size_t)(g * 32 + r) * R_DIM);
        for (int c4 = 0; c4 < R_DIM / 4; c4++) {
            float4 w4 = Wr4[c4];
            float wv[4] = {w4.x, w4.y, w4.z, w4.w};
#pragma unroll
            for (int j = 0; j < 4; j++) {
                float w = wv[j];
                if (w != 0.0f) {
                    int c = c4 * 4 + j;
                    int b = c & 31;
                    int i = bcnt[r * 32 + b]++;
                    if (i < 16) {
                        bcol[(r * 32 + b) * 16 + i] = (unsigned short)c;
                        bval[(r * 32 + b) * 16 + i] = w;
                    }
                }
            }
        }
        unsigned m = 0;
        for (int b = 0; b < 32; b++)
            if (bcnt[r * 32 + b] > 0) m |= 1u << b;
        rowmask[r] = m;
        __syncwarp();

        if (r == 0) {
            int rows_left = 0;
            for (int i = 0; i < 32; i++)
                if (rowmask[i]) rows_left++;
            int s = 0;
            while (rows_left > 0 && s < ELLCAP) {
                unsigned used = 0, pickedmask = 0;
                for (int i = 0; i < 32; i++) {
                    int rr = (s + i) & 31;
                    unsigned avail = rowmask[rr] & ~used;
                    if (avail) {
                        int b = __ffs(avail) - 1;
                        int c = --bcnt[rr * 32 + b];
                        unsigned short col = bcol[(rr * 32 + b) * 16 + c];
                        float v = bval[(rr * 32 + b) * 16 + c];
                        if (c == 0) {
                            rowmask[rr] &= ~(1u << b);
                            if (!rowmask[rr]) rows_left--;
                        }
                        used |= 1u << b;
                        pickedmask |= 1u << rr;
                        size_t idx = (size_t)(s >> 1) * R_DIM + g * 32 + rr;
                        ((float*)d_ellv2)[idx * 2 + (s & 1)] = v;
                        ((unsigned short*)d_ellc2)[idx * 2 + (s & 1)] =
                            (unsigned short)(col * 4);  // BYTE offset
                    }
                }
                unsigned freeb = ~used;
                for (int rr = 0; rr < 32; rr++) {
                    if (!((pickedmask >> rr) & 1)) {
                        int b = __ffs(freeb) - 1;
                        freeb &= freeb - 1;
                        size_t idx = (size_t)(s >> 1) * R_DIM + g * 32 + rr;
                        ((float*)d_ellv2)[idx * 2 + (s & 1)] = 0.0f;
                        ((unsigned short*)d_ellc2)[idx * 2 + (s & 1)] =
                            (unsigned short)(b * 4);
                    }
                }
                s++;
            }
            if (s & 1) {  // pad to even slot count; pads bank-distinct
                for (int rr = 0; rr < 32; rr++) {
                    size_t idx = (size_t)(s >> 1) * R_DIM + g * 32 + rr;
                    ((float*)d_ellv2)[idx * 2 + 1] = 0.0f;
                    ((unsigned short*)d_ellc2)[idx * 2 + 1] = (unsigned short)(rr * 4);
                }
                s++;
            }
            d_kgrp[g] = s;
        }
        return;
    }

    // ---------------- gemm path: U = X @ W_in^T, 64x64 tiles ---------------
    __shared__ float xs[64][68];
    __shared__ float ws[64][68];
    int gb = blockIdx.x - 32;
    int bt = (gb % GEMM_TILES_T) * 64;
    int br = (gb / GEMM_TILES_T) * 64;
    int ty = threadIdx.x >> 4;
    int tx = threadIdx.x & 15;

    float acc[4][4];
#pragma unroll
    for (int i = 0; i < 4; i++)
#pragma unroll
        for (int j = 0; j < 4; j++) acc[i][j] = 0.0f;

    for (int kc = 0; kc < I_DIM; kc += 64) {
        for (int i = threadIdx.x; i < 64 * 16; i += 256) {
            int rr = i >> 4, cc = i & 15;
            *(float4*)&xs[rr][cc * 4] = *(const float4*)&X[(size_t)(bt + rr) * I_DIM + kc + cc * 4];
            *(float4*)&ws[rr][cc * 4] = *(const float4*)&Win[(size_t)(br + rr) * I_DIM + kc + cc * 4];
        }
        __syncthreads();
#pragma unroll
        for (int k = 0; k < 64; k++) {
            float a[4], b[4];
#pragma unroll
            for (int i = 0; i < 4; i++) a[i] = xs[ty + 16 * i][k];
#pragma unroll
            for (int j = 0; j < 4; j++) b[j] = ws[tx + 16 * j][k];
#pragma unroll
            for (int i = 0; i < 4; i++)
#pragma unroll
                for (int j = 0; j < 4; j++) acc[i][j] += a[i] * b[j];
        }
        __syncthreads();
    }
#pragma unroll
    for (int i = 0; i < 4; i++)
#pragma unroll
        for (int j = 0; j < 4; j++)
            d_U[(size_t)(bt + ty + 16 * i) * R_DIM + br + tx + 16 * j] = acc[i][j];
}

// ---------------------------------------------------------------------------
// Recurrence: 8-CTA cluster, 128 threads (4 warps), one FULL row per thread.
// R7 structure verbatim; ONLY the tanh computation differs.
__global__ __launch_bounds__(RPC, 1)
void k_esn(const float* __restrict__ state0, float* __restrict__ out) {
    __shared__ float    sbuf[2 * R_DIM];          // double-buffered full state
    __shared__ float2   srv[SREM][RPC];           // remainder pairs (vals)
    __shared__ unsigned src_[SREM][RPC];          // remainder pairs (byte-off pairs)
    __shared__ unsigned long long mbar[2];
    __shared__ int kg_s[4];

    int tid = threadIdx.x;          // 0..127
    int cta = blockIdx.x;           // == cluster rank
    int grow = cta * RPC + tid;     // global row owned by this thread

    uint32_t sb_a = smaddr(sbuf);
    uint32_t mb_a = smaddr(mbar);

    if (tid < 4) {
        int v = d_kgrp[cta * 4 + tid];
        kg_s[tid] = (v > 2 * (KREG + SREM)) ? 2 * (KREG + SREM) : v;
    }
    if (tid == 0) {
        // 8 arrivals per phase barrier: one per source CTA
        asm volatile("mbarrier.init.shared.b64 [%0], %1;" :: "r"(mb_a), "r"(NCTA));
        asm volatile("mbarrier.init.shared.b64 [%0], %1;" :: "r"(mb_a + 8), "r"(NCTA));
    }
    for (int i = tid; i < R_DIM; i += RPC) sbuf[i] = state0[i];
    __syncthreads();

    // stage remainder pairs [KREG, Kp) into smem
    for (int idx = tid; idx < SREM * RPC; idx += RPC) {
        int p = KREG + idx / RPC, lr = idx % RPC;
        int kp2 = kg_s[lr >> 5] >> 1;
        if (p < kp2) {
            srv[p - KREG][lr] = d_ellv2[(size_t)p * R_DIM + cta * RPC + lr];
            src_[p - KREG][lr] = d_ellc2[(size_t)p * R_DIM + cta * RPC + lr];
        }
    }
    __syncthreads();

    // all CTAs' mbarrier.init + initial state complete before use
    asm volatile("barrier.cluster.arrive.aligned;" ::: "memory");
    asm volatile("barrier.cluster.wait.aligned;" ::: "memory");

    int Kp = kg_s[tid >> 5] >> 1;   // pair count for my row's group

    // ---- preload: values + ABSOLUTE smem addresses (buffer 0) ------------
    float    va[2 * KREG];
    uint32_t ad[2 * KREG];
    uint32_t pada = sb_a + (uint32_t)((tid & 31) * 4);  // lane-distinct pad bank
#pragma unroll
    for (int p = 0; p < KREG; p++) {
        if (p < Kp) {
            float2 v = d_ellv2[(size_t)p * R_DIM + grow];
            unsigned c = d_ellc2[(size_t)p * R_DIM + grow];
            va[2 * p] = v.x;     ad[2 * p] = sb_a + (c & 0xFFFFu);
            va[2 * p + 1] = v.y; ad[2 * p + 1] = sb_a + (c >> 16);
        } else {
            va[2 * p] = 0.0f;     ad[2 * p] = pada;
            va[2 * p + 1] = 0.0f; ad[2 * p + 1] = pada;
        }
    }

    // ---- hoisted remote addresses ----------------------------------------
    uint32_t rab[NCTA];   // peer p's sbuf slot for my row (buffer 0)
    uint32_t la0 = sb_a + (uint32_t)(grow * 4);
#pragma unroll
    for (int p = 0; p < NCTA; p++) {
        asm("mapa.shared::cluster.u32 %0, %1, %2;" : "=r"(rab[p]) : "r"(la0), "r"(p));
    }
    uint32_t raA = 0, raB = 0;  // peer tid's mbar[0], mbar[1] (tid<NCTA)
    if (tid < NCTA) {
        asm("mapa.shared::cluster.u32 %0, %1, %2;" : "=r"(raA) : "r"(mb_a), "r"(tid));
        raB = raA + 8;
    }

    float u_next = __ldg(&d_U[grow]);  // U for t=0

    for (int t = 0; t < T_STEPS; t++) {
        float u = u_next;
        int tn = (t + 1 < T_STEPS) ? (t + 1) : t;
        u_next = __ldg(&d_U[(size_t)tn * R_DIM + grow]);  // full-step cover

        float a0 = 0, a1 = 0, a2 = 0, a3 = 0, a4 = 0, a5 = 0, a6 = 0, a7 = 0;
        float s;
        if (!(t & 1)) {
            // read buf0 ([ad]), write buf1 ([rab]+4096)
#pragma unroll
            for (int e = 0; e < 2 * KREG; e += 8) {
                float x0, x1, x2, x3, x4, x5, x6, x7;
                asm volatile("ld.shared.f32 %0, [%1];" : "=f"(x0) : "r"(ad[e + 0]));
                asm volatile("ld.shared.f32 %0, [%1];" : "=f"(x1) : "r"(ad[e + 1]));
                asm volatile("ld.shared.f32 %0, [%1];" : "=f"(x2) : "r"(ad[e + 2]));
                asm volatile("ld.shared.f32 %0, [%1];" : "=f"(x3) : "r"(ad[e + 3]));
                asm volatile("ld.shared.f32 %0, [%1];" : "=f"(x4) : "r"(ad[e + 4]));
                asm volatile("ld.shared.f32 %0, [%1];" : "=f"(x5) : "r"(ad[e + 5]));
                asm volatile("ld.shared.f32 %0, [%1];" : "=f"(x6) : "r"(ad[e + 6]));
                asm volatile("ld.shared.f32 %0, [%1];" : "=f"(x7) : "r"(ad[e + 7]));
                a0 += va[e + 0] * x0; a1 += va[e + 1] * x1;
                a2 += va[e + 2] * x2; a3 += va[e + 3] * x3;
                a4 += va[e + 4] * x4; a5 += va[e + 5] * x5;
                a6 += va[e + 6] * x6; a7 += va[e + 7] * x7;
            }
            for (int p = KREG; p < Kp; p++) {  // remainder (cold at KREG=40)
                float2 v = srv[p - KREG][tid];
                unsigned c = src_[p - KREG][tid];
                a0 += v.x * sbuf[(c & 0xFFFFu) >> 2];
                a1 += v.y * sbuf[(c >> 16) >> 2];
            }
            float y = u + (((a0 + a1) + (a2 + a3)) + ((a4 + a5) + (a6 + a7)));
            asm("tanh.approx.f32 %0, %1;" : "=f"(s) : "f"(y));  // single MUFU
#pragma unroll
            for (int p = 0; p < NCTA; p++)
                asm volatile("st.shared::cluster.f32 [%0+4096], %1;" :: "r"(rab[p]), "f"(s));
        } else {
            // read buf1 ([ad]+4096), write buf0 ([rab])
#pragma unroll
            for (int e = 0; e < 2 * KREG; e += 8) {
                float x0, x1, x2, x3, x4, x5, x6, x7;
                asm volatile("ld.shared.f32 %0, [%1+4096];" : "=f"(x0) : "r"(ad[e + 0]));
                asm volatile("ld.shared.f32 %0, [%1+4096];" : "=f"(x1) : "r"(ad[e + 1]));
                asm volatile("ld.shared.f32 %0, [%1+4096];" : "=f"(x2) : "r"(ad[e + 2]));
                asm volatile("ld.shared.f32 %0, [%1+4096];" : "=f"(x3) : "r"(ad[e + 3]));
                asm volatile("ld.shared.f32 %0, [%1+4096];" : "=f"(x4) : "r"(ad[e + 4]));
                asm volatile("ld.shared.f32 %0, [%1+4096];" : "=f"(x5) : "r"(ad[e + 5]));
                asm volatile("ld.shared.f32 %0, [%1+4096];" : "=f"(x6) : "r"(ad[e + 6]));
                asm volatile("ld.shared.f32 %0, [%1+4096];" : "=f"(x7) : "r"(ad[e + 7]));
                a0 += va[e + 0] * x0; a1 += va[e + 1] * x1;
                a2 += va[e + 2] * x2; a3 += va[e + 3] * x3;
                a4 += va[e + 4] * x4; a5 += va[e + 5] * x5;
                a6 += va[e + 6] * x6; a7 += va[e + 7] * x7;
            }
            for (int p = KREG; p < Kp; p++) {  // remainder (cold at KREG=40)
                float2 v = srv[p - KREG][tid];
                unsigned c = src_[p - KREG][tid];
                a0 += v.x * sbuf[R_DIM + ((c & 0xFFFFu) >> 2)];
                a1 += v.y * sbuf[R_DIM + ((c >> 16) >> 2)];
            }
            float y = u + (((a0 + a1) + (a2 + a3)) + ((a4 + a5) + (a6 + a7)));
            asm("tanh.approx.f32 %0, %1;" : "=f"(s) : "f"(y));  // single MUFU
#pragma unroll
            for (int p = 0; p < NCTA; p++)
                asm volatile("st.shared::cluster.f32 [%0], %1;" :: "r"(rab[p]), "f"(s));
        }
        out[(size_t)t * R_DIM + grow] = s;

        __syncthreads();  // all this CTA's stores + state reads done

        if (tid < NCTA) {
            // distributed plain cluster arrive: thread p -> peer p
            uint32_t ra = (t & 1) ? raB : raA;
            asm volatile("mbarrier.arrive.shared::cluster.b64 _, [%0];" :: "r"(ra) : "memory");
        }
        uint32_t mba = mb_a + (uint32_t)((t & 1) * 8);
        unsigned parity = (t >> 1) & 1;  // each mbar flips every 2 steps
        asm volatile(
            "{ .reg .pred P;\n"
            "W%=:\n"
            " mbarrier.try_wait.parity.acquire.cluster.shared::cta.b64 P, [%0], %1, 0x989680;\n"
            " @!P bra W%=;\n"
            "}" :: "r"(mba), "r"(parity) : "memory");
    }
}

// ---------------------------------------------------------------------------
extern "C" void kernel_launch(void* const* d_in, const int* in_sizes, int n_in,
                              void* d_out, int out_size) {
    const float* X    = (const float*)d_in[0];  // (T, I)
    const float* Win  = (const float*)d_in[1];  // (R, I)
    const float* Wres = (const float*)d_in[2];  // (R, R)
    const float* s0   = (const float*)d_in[3];  // (R,)
    float* out = (float*)d_out;                 // (T, R)

    cudaFuncSetAttribute(k_prep, cudaFuncAttributeMaxDynamicSharedMemorySize, B2_SMEM);

    k_prep<<<PREP_BLOCKS, 256, B2_SMEM>>>(Wres, X, Win);

    cudaLaunchConfig_t cfg = {};
    cfg.gridDim = {NCTA, 1, 1};
    cfg.blockDim = {RPC, 1, 1};
    cfg.dynamicSmemBytes = 0;
    cudaLaunchAttribute attrs[1];
    attrs[0].id = cudaLaunchAttributeClusterDimension;
    attrs[0].val.clusterDim = {NCTA, 1, 1};
    cfg.attrs = attrs;
    cfg.numAttrs = 1;
    cudaLaunchKernelEx(&cfg, k_esn, (const float*)s0, (float*)out);
}

// round 16
// speedup vs baseline: 1.4999x; 1.0016x over previous
#include <cuda_runtime.h>
#include <cstdint>

// ESN: s_t = tanh(U_t + W_res @ s_{t-1}),  U = X @ W_in^T
// T=16384 steps, R=1024 reservoir, I=128 input. W_res ~5% dense.
//
// R15 = R14 (8.47ms best: R7 + tanh.approx.f32) with two tail micro-shavings
// (same mechanism — shorten the serial segment between last FFMA and bar):
//  1. u folded into accumulator init (a0 = u): one fewer dependent FADD.
//  2. out[] STG moved into the mbarrier-wait shadow (after arrives).
//     u_next LDG STAYS at loop top (R11 proved shortening its cover hurts).

#define T_STEPS 16384
#define R_DIM   1024
#define I_DIM   128
#define NCTA    8
#define RPC     128     // rows per CTA == threads per CTA
#define ELLCAP  192     // max slots per row (global build clamp)
#define KREG    40      // pairs held in registers per thread (covers max Kp)
#define SREM    24      // extra pairs staged in smem (KREG+SREM = 64 = clamp)

__device__ float    d_U[(size_t)T_STEPS * R_DIM];        // 64 MiB
__device__ float2   d_ellv2[(ELLCAP / 2) * R_DIM];       // pair-packed vals
__device__ unsigned d_ellc2[(ELLCAP / 2) * R_DIM];       // pair-packed BYTE offsets (2xu16)
__device__ int      d_kgrp[R_DIM / 32];                  // slots per 32-row group (even)

__device__ __forceinline__ uint32_t smaddr(const void* p) {
    uint32_t a;
    asm("{ .reg .u64 t; cvta.to.shared.u64 t, %1; cvt.u32.u64 %0, t; }"
        : "=r"(a) : "l"(p));
    return a;
}

// ---------------------------------------------------------------------------
// Fused prep kernel: blocks [0,32) build the bank-conflict-free ELL schedule
// (one warp per 32-row group); blocks [32, 32+4096) compute U = X @ W_in^T.
#define B2_BCOL 0
#define B2_BVAL (32 * 32 * 16 * 2)
#define B2_BCNT (B2_BVAL + 32 * 32 * 16 * 4)
#define B2_MASK (B2_BCNT + 32 * 32 * 4)
#define B2_SMEM (B2_MASK + 32 * 4)
#define GEMM_TILES_T (T_STEPS / 64)
#define GEMM_TILES_R (R_DIM / 64)
#define PREP_BLOCKS (32 + GEMM_TILES_T * GEMM_TILES_R)

__global__ __launch_bounds__(256) void k_prep(const float* __restrict__ W,
                                              const float* __restrict__ X,
                                              const float* __restrict__ Win) {
    if (blockIdx.x < 32) {
        if (threadIdx.x >= 32) return;
        extern __shared__ unsigned char sm[];
        unsigned short* bcol    = (unsigned short*)(sm + B2_BCOL);  // [r][b][16]
        float*          bval    = (float*)(sm + B2_BVAL);           // [r][b][16]
        int*            bcnt    = (int*)(sm + B2_BCNT);             // [r][b]
        unsigned*       rowmask = (unsigned*)(sm + B2_MASK);        // [r]

        int g = blockIdx.x;
        int r = threadIdx.x;  // 0..31

        for (int b = 0; b < 32; b++) bcnt[r * 32 + b] = 0;
        const float4* Wr4 = (const float4*)(W + (size_t)(g * 32 + r) * R_DIM);
        for (int c4 = 0; c4 < R_DIM / 4; c4++) {
            float4 w4 = Wr4[c4];
            float wv[4] = {w4.x, w4.y, w4.z, w4.w};
#pragma unroll
            for (int j = 0; j < 4; j++) {
                float w = wv[j];
                if (w != 0.0f) {
                    int c = c4 * 4 + j;
                    int b = c & 31;
                    int i = bcnt[r * 32 + b]++;
                    if (i < 16) {
                        bcol[(r * 32 + b) * 16 + i] = (unsigned short)c;
                        bval[(r * 32 + b) * 16 + i] = w;
                    }
                }
            }
        }
        unsigned m = 0;
        for (int b = 0; b < 32; b++)
            if (bcnt[r * 32 + b] > 0) m |= 1u << b;
        rowmask[r] = m;
        __syncwarp();

        if (r == 0) {
            int rows_left = 0;
            for (int i = 0; i < 32; i++)
                if (rowmask[i]) rows_left++;
            int s = 0;
            while (rows_left > 0 && s < ELLCAP) {
                unsigned used = 0, pickedmask = 0;
                for (int i = 0; i < 32; i++) {
                    int rr = (s + i) & 31;
                    unsigned avail = rowmask[rr] & ~used;
                    if (avail) {
                        int b = __ffs(avail) - 1;
                        int c = --bcnt[rr * 32 + b];
                        unsigned short col = bcol[(rr * 32 + b) * 16 + c];
                        float v = bval[(rr * 32 + b) * 16 + c];
                        if (c == 0) {
                            rowmask[rr] &= ~(1u << b);
                            if (!rowmask[rr]) rows_left--;
                        }
                        used |= 1u << b;
                        pickedmask |= 1u << rr;
                        size_t idx = (size_t)(s >> 1) * R_DIM + g * 32 + rr;
                        ((float*)d_ellv2)[idx * 2 + (s & 1)] = v;
                        ((unsigned short*)d_ellc2)[idx * 2 + (s & 1)] =
                            (unsigned short)(col * 4);  // BYTE offset
                    }
                }
                unsigned freeb = ~used;
                for (int rr = 0; rr < 32; rr++) {
                    if (!((pickedmask >> rr) & 1)) {
                        int b = __ffs(freeb) - 1;
                        freeb &= freeb - 1;
                        size_t idx = (size_t)(s >> 1) * R_DIM + g * 32 + rr;
                        ((float*)d_ellv2)[idx * 2 + (s & 1)] = 0.0f;
                        ((unsigned short*)d_ellc2)[idx * 2 + (s & 1)] =
                            (unsigned short)(b * 4);
                    }
                }
                s++;
            }
            if (s & 1) {  // pad to even slot count; pads bank-distinct
                for (int rr = 0; rr < 32; rr++) {
                    size_t idx = (size_t)(s >> 1) * R_DIM + g * 32 + rr;
                    ((float*)d_ellv2)[idx * 2 + 1] = 0.0f;
                    ((unsigned short*)d_ellc2)[idx * 2 + 1] = (unsigned short)(rr * 4);
                }
                s++;
            }
            d_kgrp[g] = s;
        }
        return;
    }

    // ---------------- gemm path: U = X @ W_in^T, 64x64 tiles ---------------
    __shared__ float xs[64][68];
    __shared__ float ws[64][68];
    int gb = blockIdx.x - 32;
    int bt = (gb % GEMM_TILES_T) * 64;
    int br = (gb / GEMM_TILES_T) * 64;
    int ty = threadIdx.x >> 4;
    int tx = threadIdx.x & 15;

    float acc[4][4];
#pragma unroll
    for (int i = 0; i < 4; i++)
#pragma unroll
        for (int j = 0; j < 4; j++) acc[i][j] = 0.0f;

    for (int kc = 0; kc < I_DIM; kc += 64) {
        for (int i = threadIdx.x; i < 64 * 16; i += 256) {
            int rr = i >> 4, cc = i & 15;
            *(float4*)&xs[rr][cc * 4] = *(const float4*)&X[(size_t)(bt + rr) * I_DIM + kc + cc * 4];
            *(float4*)&ws[rr][cc * 4] = *(const float4*)&Win[(size_t)(br + rr) * I_DIM + kc + cc * 4];
        }
        __syncthreads();
#pragma unroll
        for (int k = 0; k < 64; k++) {
            float a[4], b[4];
#pragma unroll
            for (int i = 0; i < 4; i++) a[i] = xs[ty + 16 * i][k];
#pragma unroll
            for (int j = 0; j < 4; j++) b[j] = ws[tx + 16 * j][k];
#pragma unroll
            for (int i = 0; i < 4; i++)
#pragma unroll
                for (int j = 0; j < 4; j++) acc[i][j] += a[i] * b[j];
        }
        __syncthreads();
    }
#pragma unroll
    for (int i = 0; i < 4; i++)
#pragma unroll
        for (int j = 0; j < 4; j++)
            d_U[(size_t)(bt + ty + 16 * i) * R_DIM + br + tx + 16 * j] = acc[i][j];
}

// ---------------------------------------------------------------------------
// Recurrence: 8-CTA cluster, 128 threads (4 warps), one FULL row per thread.
__global__ __launch_bounds__(RPC, 1)
void k_esn(const float* __restrict__ state0, float* __restrict__ out) {
    __shared__ float    sbuf[2 * R_DIM];          // double-buffered full state
    __shared__ float2   srv[SREM][RPC];           // remainder pairs (vals)
    __shared__ unsigned src_[SREM][RPC];          // remainder pairs (byte-off pairs)
    __shared__ unsigned long long mbar[2];
    __shared__ int kg_s[4];

    int tid = threadIdx.x;          // 0..127
    int cta = blockIdx.x;           // == cluster rank
    int grow = cta * RPC + tid;     // global row owned by this thread

    uint32_t sb_a = smaddr(sbuf);
    uint32_t mb_a = smaddr(mbar);

    if (tid < 4) {
        int v = d_kgrp[cta * 4 + tid];
        kg_s[tid] = (v > 2 * (KREG + SREM)) ? 2 * (KREG + SREM) : v;
    }
    if (tid == 0) {
        // 8 arrivals per phase barrier: one per source CTA
        asm volatile("mbarrier.init.shared.b64 [%0], %1;" :: "r"(mb_a), "r"(NCTA));
        asm volatile("mbarrier.init.shared.b64 [%0], %1;" :: "r"(mb_a + 8), "r"(NCTA));
    }
    for (int i = tid; i < R_DIM; i += RPC) sbuf[i] = state0[i];
    __syncthreads();

    // stage remainder pairs [KREG, Kp) into smem
    for (int idx = tid; idx < SREM * RPC; idx += RPC) {
        int p = KREG + idx / RPC, lr = idx % RPC;
        int kp2 = kg_s[lr >> 5] >> 1;
        if (p < kp2) {
            srv[p - KREG][lr] = d_ellv2[(size_t)p * R_DIM + cta * RPC + lr];
            src_[p - KREG][lr] = d_ellc2[(size_t)p * R_DIM + cta * RPC + lr];
        }
    }
    __syncthreads();

    // all CTAs' mbarrier.init + initial state complete before use
    asm volatile("barrier.cluster.arrive.aligned;" ::: "memory");
    asm volatile("barrier.cluster.wait.aligned;" ::: "memory");

    int Kp = kg_s[tid >> 5] >> 1;   // pair count for my row's group

    // ---- preload: values + ABSOLUTE smem addresses (buffer 0) ------------
    float    va[2 * KREG];
    uint32_t ad[2 * KREG];
    uint32_t pada = sb_a + (uint32_t)((tid & 31) * 4);  // lane-distinct pad bank
#pragma unroll
    for (int p = 0; p < KREG; p++) {
        if (p < Kp) {
            float2 v = d_ellv2[(size_t)p * R_DIM + grow];
            unsigned c = d_ellc2[(size_t)p * R_DIM + grow];
            va[2 * p] = v.x;     ad[2 * p] = sb_a + (c & 0xFFFFu);
            va[2 * p + 1] = v.y; ad[2 * p + 1] = sb_a + (c >> 16);
        } else {
            va[2 * p] = 0.0f;     ad[2 * p] = pada;
            va[2 * p + 1] = 0.0f; ad[2 * p + 1] = pada;
        }
    }

    // ---- hoisted remote addresses ----------------------------------------
    uint32_t rab[NCTA];   // peer p's sbuf slot for my row (buffer 0)
    uint32_t la0 = sb_a + (uint32_t)(grow * 4);
#pragma unroll
    for (int p = 0; p < NCTA; p++) {
        asm("mapa.shared::cluster.u32 %0, %1, %2;" : "=r"(rab[p]) : "r"(la0), "r"(p));
    }
    uint32_t raA = 0, raB = 0;  // peer tid's mbar[0], mbar[1] (tid<NCTA)
    if (tid < NCTA) {
        asm("mapa.shared::cluster.u32 %0, %1, %2;" : "=r"(raA) : "r"(mb_a), "r"(tid));
        raB = raA + 8;
    }

    float u_next = __ldg(&d_U[grow]);  // U for t=0

    for (int t = 0; t < T_STEPS; t++) {
        float u = u_next;
        int tn = (t + 1 < T_STEPS) ? (t + 1) : t;
        u_next = __ldg(&d_U[(size_t)tn * R_DIM + grow]);  // full-step cover

        // u folded into a0: one fewer dependent FADD in the serial tail
        float a0 = u, a1 = 0, a2 = 0, a3 = 0, a4 = 0, a5 = 0, a6 = 0, a7 = 0;
        float s;
        if (!(t & 1)) {
            // read buf0 ([ad]), write buf1 ([rab]+4096)
#pragma unroll
            for (int e = 0; e < 2 * KREG; e += 8) {
                float x0, x1, x2, x3, x4, x5, x6, x7;
                asm volatile("ld.shared.f32 %0, [%1];" : "=f"(x0) : "r"(ad[e + 0]));
                asm volatile("ld.shared.f32 %0, [%1];" : "=f"(x1) : "r"(ad[e + 1]));
                asm volatile("ld.shared.f32 %0, [%1];" : "=f"(x2) : "r"(ad[e + 2]));
                asm volatile("ld.shared.f32 %0, [%1];" : "=f"(x3) : "r"(ad[e + 3]));
                asm volatile("ld.shared.f32 %0, [%1];" : "=f"(x4) : "r"(ad[e + 4]));
                asm volatile("ld.shared.f32 %0, [%1];" : "=f"(x5) : "r"(ad[e + 5]));
                asm volatile("ld.shared.f32 %0, [%1];" : "=f"(x6) : "r"(ad[e + 6]));
                asm volatile("ld.shared.f32 %0, [%1];" : "=f"(x7) : "r"(ad[e + 7]));
                a0 += va[e + 0] * x0; a1 += va[e + 1] * x1;
                a2 += va[e + 2] * x2; a3 += va[e + 3] * x3;
                a4 += va[e + 4] * x4; a5 += va[e + 5] * x5;
                a6 += va[e + 6] * x6; a7 += va[e + 7] * x7;
            }
            for (int p = KREG; p < Kp; p++) {  // remainder (cold at KREG=40)
                float2 v = srv[p - KREG][tid];
                unsigned c = src_[p - KREG][tid];
                a0 += v.x * sbuf[(c & 0xFFFFu) >> 2];
                a1 += v.y * sbuf[(c >> 16) >> 2];
            }
            float y = (((a0 + a1) + (a2 + a3)) + ((a4 + a5) + (a6 + a7)));
            asm("tanh.approx.f32 %0, %1;" : "=f"(s) : "f"(y));  // single MUFU
#pragma unroll
            for (int p = 0; p < NCTA; p++)
                asm volatile("st.shared::cluster.f32 [%0+4096], %1;" :: "r"(rab[p]), "f"(s));
        } else {
            // read buf1 ([ad]+4096), write buf0 ([rab])
#pragma unroll
            for (int e = 0; e < 2 * KREG; e += 8) {
                float x0, x1, x2, x3, x4, x5, x6, x7;
                asm volatile("ld.shared.f32 %0, [%1+4096];" : "=f"(x0) : "r"(ad[e + 0]));
                asm volatile("ld.shared.f32 %0, [%1+4096];" : "=f"(x1) : "r"(ad[e + 1]));
                asm volatile("ld.shared.f32 %0, [%1+4096];" : "=f"(x2) : "r"(ad[e + 2]));
                asm volatile("ld.shared.f32 %0, [%1+4096];" : "=f"(x3) : "r"(ad[e + 3]));
                asm volatile("ld.shared.f32 %0, [%1+4096];" : "=f"(x4) : "r"(ad[e + 4]));
                asm volatile("ld.shared.f32 %0, [%1+4096];" : "=f"(x5) : "r"(ad[e + 5]));
                asm volatile("ld.shared.f32 %0, [%1+4096];" : "=f"(x6) : "r"(ad[e + 6]));
                asm volatile("ld.shared.f32 %0, [%1+4096];" : "=f"(x7) : "r"(ad[e + 7]));
                a0 += va[e + 0] * x0; a1 += va[e + 1] * x1;
                a2 += va[e + 2] * x2; a3 += va[e + 3] * x3;
                a4 += va[e + 4] * x4; a5 += va[e + 5] * x5;
                a6 += va[e + 6] * x6; a7 += va[e + 7] * x7;
            }
            for (int p = KREG; p < Kp; p++) {  // remainder (cold at KREG=40)
                float2 v = srv[p - KREG][tid];
                unsigned c = src_[p - KREG][tid];
                a0 += v.x * sbuf[R_DIM + ((c & 0xFFFFu) >> 2)];
                a1 += v.y * sbuf[R_DIM + ((c >> 16) >> 2)];
            }
            float y = (((a0 + a1) + (a2 + a3)) + ((a4 + a5) + (a6 + a7)));
            asm("tanh.approx.f32 %0, %1;" : "=f"(s) : "f"(y));  // single MUFU
#pragma unroll
            for (int p = 0; p < NCTA; p++)
                asm volatile("st.shared::cluster.f32 [%0], %1;" :: "r"(rab[p]), "f"(s));
        }

        __syncthreads();  // all this CTA's stores + state reads done

        if (tid < NCTA) {
            // distributed plain cluster arrive: thread p -> peer p
            uint32_t ra = (t & 1) ? raB : raA;
            asm volatile("mbarrier.arrive.shared::cluster.b64 _, [%0];" :: "r"(ra) : "memory");
        }

        // fire-and-forget output store in the wait shadow (no consumer;
        // cannot delay the already-issued arrives)
        out[(size_t)t * R_DIM + grow] = s;

        uint32_t mba = mb_a + (uint32_t)((t & 1) * 8);
        unsigned parity = (t >> 1) & 1;  // each mbar flips every 2 steps
        asm volatile(
            "{ .reg .pred P;\n"
            "W%=:\n"
            " mbarrier.try_wait.parity.acquire.cluster.shared::cta.b64 P, [%0], %1, 0x989680;\n"
            " @!P bra W%=;\n"
            "}" :: "r"(mba), "r"(parity) : "memory");
    }
}

// ---------------------------------------------------------------------------
extern "C" void kernel_launch(void* const* d_in, const int* in_sizes, int n_in,
                              void* d_out, int out_size) {
    const float* X    = (const float*)d_in[0];  // (T, I)
    const float* Win  = (const float*)d_in[1];  // (R, I)
    const float* Wres = (const float*)d_in[2];  // (R, R)
    const float* s0   = (const float*)d_in[3];  // (R,)
    float* out = (float*)d_out;                 // (T, R)

    cudaFuncSetAttribute(k_prep, cudaFuncAttributeMaxDynamicSharedMemorySize, B2_SMEM);

    k_prep<<<PREP_BLOCKS, 256, B2_SMEM>>>(Wres, X, Win);

    cudaLaunchConfig_t cfg = {};
    cfg.gridDim = {NCTA, 1, 1};
    cfg.blockDim = {RPC, 1, 1};
    cfg.dynamicSmemBytes = 0;
    cudaLaunchAttribute attrs[1];
    attrs[0].id = cudaLaunchAttributeClusterDimension;
    attrs[0].val.clusterDim = {NCTA, 1, 1};
    cfg.attrs = attrs;
    cfg.numAttrs = 1;
    cudaLaunchKernelEx(&cfg, k_esn, (const float*)s0, (float*)out);
}